// round 3
// baseline (speedup 1.0000x reference)
#include <cuda_runtime.h>

#define N_NODES 50000
#define NE      800000
#define HD      64
#define TSTEPS  4
#define STRIDE  68   // 64 + 4 pad: 16B-aligned float4 rows, bank spread

// ---------- device scratch (no allocations allowed) ----------
__device__ float g_deg[N_NODES];
__device__ float g_sw[N_NODES];
__device__ float g_c3[TSTEPS * HD];
__device__ float g_S[HD];
__device__ float g_c;

// ---------- tiny kernels ----------
__global__ void init_kernel() {
    int i = blockIdx.x * blockDim.x + threadIdx.x;
    if (i < N_NODES) { g_deg[i] = 0.f; g_sw[i] = 0.f; }
    if (i < HD) g_S[i] = 0.f;
}

// edge_index arrives as int32 (JAX default x64-disabled downgrades int64).
__global__ void edge_kernel(const int* __restrict__ ei,
                            const float* __restrict__ ew) {
    int e = blockIdx.x * blockDim.x + threadIdx.x;
    if (e < NE) {
        int v = ei[NE + e];             // edge_index row 1
        if (v >= 0 && v < N_NODES) {
            atomicAdd(&g_deg[v], 1.0f);
            atomicAdd(&g_sw[v], ew[e]);
        }
    }
}

// c3[t][h] = sum_k W3[t,h,k] * relu(W4[t,k]);  one block per t
__global__ void c3_kernel(const float* __restrict__ W3,
                          const float* __restrict__ W4) {
    __shared__ float rw4[HD];
    int t = blockIdx.x;
    int h = threadIdx.x;
    rw4[h] = fmaxf(W4[t * HD + h], 0.f);
    __syncthreads();
    float s = 0.f;
    const float* row = W3 + t * HD * HD + h * HD;
#pragma unroll 16
    for (int k = 0; k < HD; k++) s = fmaf(row[k], rw4[k], s);
    g_c3[t * HD + h] = s;
}

// ---------- fused kernel: 4 S2V steps + final readout, one 64-row tile/block ----------
__global__ void __launch_bounds__(256)
fused_kernel(const float* __restrict__ mu, const float* __restrict__ x,
             const float* __restrict__ W1, const float* __restrict__ W2,
             const float* __restrict__ W5, const float* __restrict__ W7,
             float* __restrict__ out) {
    __shared__ __align__(16) float Ws[HD][STRIDE];    // weights transposed: Ws[k][h]
    __shared__ __align__(16) float muT[HD][STRIDE];   // tile transposed: muT[k][row]
    __shared__ float xs[64], degs[64], sws[64];
    __shared__ float w1s[64], c3s[64];
    __shared__ float red[64][17];
    __shared__ float colp[4][64];

    const int tid = threadIdx.x;
    const int tx = tid & 15;     // column group: cols tx*4 .. tx*4+3
    const int ty = tid >> 4;     // row group:    rows ty*4 .. ty*4+3
    const int c0 = tx * 4;
    const int r0 = ty * 4;
    const int v0 = blockIdx.x * 64;

    // load mu tile (coalesced global reads, transposed smem writes)
    for (int i = tid; i < 64 * 64; i += 256) {
        int r = i >> 6, k = i & 63;
        int v = v0 + r;
        muT[k][r] = (v < N_NODES) ? mu[v * 64 + k] : 0.f;
    }
    if (tid < 64) {
        int v = v0 + tid;
        xs[tid]   = (v < N_NODES) ? x[v]     : 0.f;
        degs[tid] = (v < N_NODES) ? g_deg[v] : 0.f;
        sws[tid]  = (v < N_NODES) ? g_sw[v]  : 0.f;
    }

    for (int t = 0; t < TSTEPS; t++) {
        __syncthreads();
        // load W2[t]^T
        for (int i = tid; i < 64 * 64; i += 256)
            Ws[i & 63][i >> 6] = W2[t * 4096 + i];
        if (tid < 64) { w1s[tid] = W1[t * 64 + tid]; c3s[tid] = g_c3[t * 64 + tid]; }
        __syncthreads();

        float acc[4][4];
#pragma unroll
        for (int i = 0; i < 4; i++)
#pragma unroll
            for (int j = 0; j < 4; j++) acc[i][j] = 0.f;

#pragma unroll 8
        for (int k = 0; k < 64; k++) {
            float4 w = *(const float4*)&Ws[k][c0];
            float4 m = *(const float4*)&muT[k][r0];
            acc[0][0] = fmaf(w.x, m.x, acc[0][0]);
            acc[0][1] = fmaf(w.x, m.y, acc[0][1]);
            acc[0][2] = fmaf(w.x, m.z, acc[0][2]);
            acc[0][3] = fmaf(w.x, m.w, acc[0][3]);
            acc[1][0] = fmaf(w.y, m.x, acc[1][0]);
            acc[1][1] = fmaf(w.y, m.y, acc[1][1]);
            acc[1][2] = fmaf(w.y, m.z, acc[1][2]);
            acc[1][3] = fmaf(w.y, m.w, acc[1][3]);
            acc[2][0] = fmaf(w.z, m.x, acc[2][0]);
            acc[2][1] = fmaf(w.z, m.y, acc[2][1]);
            acc[2][2] = fmaf(w.z, m.z, acc[2][2]);
            acc[2][3] = fmaf(w.z, m.w, acc[2][3]);
            acc[3][0] = fmaf(w.w, m.x, acc[3][0]);
            acc[3][1] = fmaf(w.w, m.y, acc[3][1]);
            acc[3][2] = fmaf(w.w, m.z, acc[3][2]);
            acc[3][3] = fmaf(w.w, m.w, acc[3][3]);
        }
        __syncthreads();   // all reads of muT done before overwriting

        // epilogue: mu' = relu(x*w1 + deg*(mu@W2^T) + sw*c3), write transposed
#pragma unroll
        for (int i = 0; i < 4; i++) {
            int c = c0 + i;
            float w1c = w1s[c], c3c = c3s[c];
#pragma unroll
            for (int j = 0; j < 4; j++) {
                int r = r0 + j;
                float vv = fmaf(xs[r], w1c, fmaf(degs[r], acc[i][j], sws[r] * c3c));
                muT[c][r] = fmaxf(vv, 0.f);
            }
        }
    }
    __syncthreads();

    // column partial sums of final mu (for graph pool)
    {
        int h = tid & 63, g = tid >> 6;
        float s = 0.f;
#pragma unroll
        for (int j = 0; j < 16; j++) s += muT[h][g * 16 + j];
        colp[g][h] = s;
    }
    // load W7^T and W5 node-half (disjoint smem regions)
    for (int i = tid; i < 64 * 64; i += 256)
        Ws[i & 63][i >> 6] = W7[i];
    if (tid < 64) w1s[tid] = W5[64 + tid];
    __syncthreads();

    if (tid < 64)
        atomicAdd(&g_S[tid], colp[0][tid] + colp[1][tid] + colp[2][tid] + colp[3][tid]);

    // final GEMM: nodes_vec = mu @ W7^T
    float acc[4][4];
#pragma unroll
    for (int i = 0; i < 4; i++)
#pragma unroll
        for (int j = 0; j < 4; j++) acc[i][j] = 0.f;

#pragma unroll 8
    for (int k = 0; k < 64; k++) {
        float4 w = *(const float4*)&Ws[k][c0];
        float4 m = *(const float4*)&muT[k][r0];
        acc[0][0] = fmaf(w.x, m.x, acc[0][0]);
        acc[0][1] = fmaf(w.x, m.y, acc[0][1]);
        acc[0][2] = fmaf(w.x, m.z, acc[0][2]);
        acc[0][3] = fmaf(w.x, m.w, acc[0][3]);
        acc[1][0] = fmaf(w.y, m.x, acc[1][0]);
        acc[1][1] = fmaf(w.y, m.y, acc[1][1]);
        acc[1][2] = fmaf(w.y, m.z, acc[1][2]);
        acc[1][3] = fmaf(w.y, m.w, acc[1][3]);
        acc[2][0] = fmaf(w.z, m.x, acc[2][0]);
        acc[2][1] = fmaf(w.z, m.y, acc[2][1]);
        acc[2][2] = fmaf(w.z, m.z, acc[2][2]);
        acc[2][3] = fmaf(w.z, m.w, acc[2][3]);
        acc[3][0] = fmaf(w.w, m.x, acc[3][0]);
        acc[3][1] = fmaf(w.w, m.y, acc[3][1]);
        acc[3][2] = fmaf(w.w, m.z, acc[3][2]);
        acc[3][3] = fmaf(w.w, m.w, acc[3][3]);
    }

    // per-row partial: sum_c relu(nv)*W5b[c]
    float pr[4] = {0.f, 0.f, 0.f, 0.f};
#pragma unroll
    for (int i = 0; i < 4; i++) {
        float wb = w1s[c0 + i];
#pragma unroll
        for (int j = 0; j < 4; j++)
            pr[j] = fmaf(fmaxf(acc[i][j], 0.f), wb, pr[j]);
    }
    red[r0 + 0][tx] = pr[0];
    red[r0 + 1][tx] = pr[1];
    red[r0 + 2][tx] = pr[2];
    red[r0 + 3][tx] = pr[3];
    __syncthreads();

    if (tid < 64) {
        float s = 0.f;
#pragma unroll
        for (int q = 0; q < 16; q++) s += red[tid][q];
        int v = v0 + tid;
        if (v < N_NODES) out[v] = s;
    }
}

// graph-pool scalar: c = sum_h relu(S[h]) * W5[h]
__global__ void scalar_kernel(const float* __restrict__ W5) {
    __shared__ float sh[HD];
    int h = threadIdx.x;
    sh[h] = fmaxf(g_S[h], 0.f) * W5[h];
    __syncthreads();
    if (h == 0) {
        float s = 0.f;
#pragma unroll
        for (int i = 0; i < HD; i++) s += sh[i];
        g_c = s;
    }
}

__global__ void add_kernel(float* __restrict__ out) {
    int v = blockIdx.x * blockDim.x + threadIdx.x;
    if (v < N_NODES) out[v] += g_c;
}

// ---------- launch ----------
extern "C" void kernel_launch(void* const* d_in, const int* in_sizes, int n_in,
                              void* d_out, int out_size) {
    const float* mu = (const float*)d_in[0];
    const float* x  = (const float*)d_in[1];
    const int*   ei = (const int*)d_in[2];     // int32! (JAX x64 disabled)
    const float* ew = (const float*)d_in[3];
    const float* W1 = (const float*)d_in[4];
    const float* W2 = (const float*)d_in[5];
    const float* W3 = (const float*)d_in[6];
    const float* W4 = (const float*)d_in[7];
    const float* W5 = (const float*)d_in[8];
    const float* W7 = (const float*)d_in[9];
    float* out = (float*)d_out;

    init_kernel<<<(N_NODES + 255) / 256, 256>>>();
    edge_kernel<<<(NE + 255) / 256, 256>>>(ei, ew);
    c3_kernel<<<TSTEPS, HD>>>(W3, W4);
    fused_kernel<<<(N_NODES + 63) / 64, 256>>>(mu, x, W1, W2, W5, W7, out);
    scalar_kernel<<<1, HD>>>(W5);
    add_kernel<<<(N_NODES + 255) / 256, 256>>>(out);
}